// round 15
// baseline (speedup 1.0000x reference)
#include <cuda_runtime.h>
#include <cuda_fp16.h>
#include <math.h>
#include <cstdint>

// ---------------------------------------------------------------------------
// Problem constants
// ---------------------------------------------------------------------------
#define BATCH 64
#define NPTS  4096

constexpr int S1 = 500, S2 = 250, S3 = 125;
constexpr int M1 = BATCH * S1;   // 32000
constexpr int M2 = BATCH * S2;   // 16000
constexpr int M3 = BATCH * S3;   // 8000

// ---------------------------------------------------------------------------
// Float scratch: sampled coords + composed biases
// ---------------------------------------------------------------------------
constexpr size_t OFF_NX1 = 0;                          // [M1,3]
constexpr size_t OFF_NX2 = OFF_NX1 + (size_t)M1 * 3;   // [M2,3]
constexpr size_t OFF_B3  = OFF_NX2 + (size_t)M2 * 3;   // [256]
constexpr size_t OFF_B5  = OFF_B3 + 256;               // [384]
constexpr size_t SCRATCH_SZ = OFF_B5 + 384;

// ---------------------------------------------------------------------------
// Half buffer: activations + fp16 weights [N][Kpad] (zero-padded).
// ---------------------------------------------------------------------------
constexpr size_t HOFF_H1  = 0;                              // [M1,64]
constexpr size_t HOFF_L2G = HOFF_H1  + (size_t)M1 * 64;     // [M1,256]
constexpr size_t HOFF_L4  = HOFF_L2G + (size_t)M1 * 256;    // [M1,256]
constexpr size_t HOFF_L5  = HOFF_L4  + (size_t)M1 * 256;    // [M1,384]
constexpr size_t HOFF_L7  = HOFF_L5  + (size_t)M1 * 384;    // [M2,384]
constexpr size_t HOFF_WC  = HOFF_L7  + (size_t)M2 * 384;
constexpr int WC_W2  = 0;        // Kpad  64, N 256
constexpr int WC_W3C = 16384;    // Kpad 256, N 256  (pc1w @ w3[3:259])
constexpr int WC_W4  = 81920;    // Kpad 256, N 384
constexpr int WC_W5C = 180224;   // Kpad 384, N 384  (pc2w @ w5[3:387])
constexpr int WC_W6  = 327680;   // Kpad 384, N 512
constexpr int WC_TOTAL = 524288;
constexpr int WCONV_TOTAL = 16384 + 98304 + 196608;  // w2 + w4 + w6
constexpr size_t HBUF_SZ = HOFF_WC + WC_TOTAL;

__device__ __align__(256) float  g_scratch[SCRATCH_SZ];
__device__ __align__(256) __half g_hbuf[HBUF_SZ];
__device__ int g_idx[M1 + M2 + M3];
constexpr int IDX1 = 0, IDX2 = M1, IDX3 = M1 + M2;

// ---------------------------------------------------------------------------
// PTX helpers
// ---------------------------------------------------------------------------
__device__ __forceinline__ void mma16n8k16(float* c, const uint32_t* a, const uint32_t* b) {
    asm volatile(
        "mma.sync.aligned.m16n8k16.row.col.f32.f16.f16.f32 "
        "{%0,%1,%2,%3}, {%4,%5,%6,%7}, {%8,%9}, {%0,%1,%2,%3};"
        : "+f"(c[0]), "+f"(c[1]), "+f"(c[2]), "+f"(c[3])
        : "r"(a[0]), "r"(a[1]), "r"(a[2]), "r"(a[3]), "r"(b[0]), "r"(b[1]));
}
__device__ __forceinline__ void ldsm4(uint32_t& r0, uint32_t& r1, uint32_t& r2,
                                      uint32_t& r3, uint32_t addr) {
    asm volatile("ldmatrix.sync.aligned.m8n8.x4.shared.b16 {%0,%1,%2,%3}, [%4];"
                 : "=r"(r0), "=r"(r1), "=r"(r2), "=r"(r3) : "r"(addr));
}
__device__ __forceinline__ uint32_t smem_u32(const void* p) {
    uint32_t a;
    asm("{ .reg .u64 t; cvta.to.shared.u64 t, %1; cvt.u32.u64 %0, t; }"
        : "=r"(a) : "l"(p));
    return a;
}
__device__ __forceinline__ void cpa16(uint32_t dst, const __half* src) {
    asm volatile("cp.async.ca.shared.global [%0], [%1], 16;"
                 :: "r"(dst), "l"(src) : "memory");
}
__device__ __forceinline__ void cpa_commit() {
    asm volatile("cp.async.commit_group;" ::: "memory");
}
__device__ __forceinline__ void cpa_wait2() {
    asm volatile("cp.async.wait_group 2;" ::: "memory");
}
__device__ __forceinline__ uint32_t redux_max(uint32_t v) {
    uint32_t r;
    asm volatile("redux.sync.max.u32 %0, %1, 0xffffffff;" : "=r"(r) : "r"(v));
    return r;
}
__device__ __forceinline__ uint32_t redux_min(uint32_t v) {
    uint32_t r;
    asm volatile("redux.sync.min.u32 %0, %1, 0xffffffff;" : "=r"(r) : "r"(v));
    return r;
}

// ---------------------------------------------------------------------------
// Confidence MLP (all points) + zero-init of the (B,512) max-pool output
// ---------------------------------------------------------------------------
__global__ void conf_kernel(const float* __restrict__ x,
                            const float* __restrict__ cw1,
                            const float* __restrict__ cb1,
                            const float* __restrict__ cw2,
                            const float* __restrict__ cb2,
                            float* __restrict__ conf,
                            float* __restrict__ outz)
{
    int p = blockIdx.x * blockDim.x + threadIdx.x;
    if (p < BATCH * 512) outz[p] = 0.f;
    if (p >= BATCH * NPTS) return;
    float x0 = x[3 * p], x1 = x[3 * p + 1], x2 = x[3 * p + 2];
    float acc = 0.f;
#pragma unroll 8
    for (int j = 0; j < 64; j++) {
        float h = cb1[j] + x0 * cw1[j] + x1 * cw1[64 + j] + x2 * cw1[128 + j];
        h = fmaxf(h, 0.f);
        acc += h * cw2[j];
    }
    float z = acc + cb2[0];
    conf[p] = 1.f / (1.f + expf(-z));
}

// ---------------------------------------------------------------------------
// Plain weight transposes -> fp16 [N][Kpad] (w2, w4, w6)
// ---------------------------------------------------------------------------
__global__ void wconv_kernel(const float* __restrict__ w2, const float* __restrict__ w4,
                             const float* __restrict__ w6)
{
    int e = blockIdx.x * blockDim.x + threadIdx.x;
    if (e >= WCONV_TOTAL) return;
    const float* src; int base, N, K, local;
    if (e < 16384)       { src = w2; base = WC_W2; N = 256; K = 64;  local = e; }
    else if (e < 114688) { src = w4; base = WC_W4; N = 384; K = 256; local = e - 16384; }
    else                 { src = w6; base = WC_W6; N = 512; K = 384; local = e - 114688; }
    int n = local / K, k = local - n * K;
    g_hbuf[HOFF_WC + base + (size_t)n * K + k] =
        __float2half_rn(__ldg(&src[(size_t)k * N + n]));
}

// ---------------------------------------------------------------------------
// Composed weight products: Wc[n][k] = sum_j pw[k][j] * w[(3+j)*N + n]
// ---------------------------------------------------------------------------
__global__ void wprod_kernel(int out_base, const float* __restrict__ pw,
                             const float* __restrict__ w, int N, int J, int K)
{
    int e = blockIdx.x * blockDim.x + threadIdx.x;
    if (e >= N * K) return;
    int n = e % N, k = e / N;
    const float* pwr = pw + (size_t)k * J;
    float acc = 0.f;
#pragma unroll 4
    for (int j = 0; j < J; j++)
        acc += __ldg(&pwr[j]) * __ldg(&w[(size_t)(3 + j) * N + n]);
    g_hbuf[HOFF_WC + out_base + (size_t)n * K + k] = __float2half_rn(acc);
}

// Composed biases: b' = b + pb @ w[3:,:]
__global__ void wbias_kernel(const float* __restrict__ pc1b, const float* __restrict__ w3,
                             const float* __restrict__ b3,
                             const float* __restrict__ pc2b, const float* __restrict__ w5,
                             const float* __restrict__ b5)
{
    int n = blockIdx.x * blockDim.x + threadIdx.x;
    if (n < 256) {
        float acc = b3[n];
        for (int j = 0; j < 256; j++) acc += pc1b[j] * __ldg(&w3[(size_t)(3 + j) * 256 + n]);
        g_scratch[OFF_B3 + n] = acc;
    } else if (n < 640) {
        int m = n - 256;
        float acc = b5[m];
        for (int j = 0; j < 384; j++) acc += pc2b[j] * __ldg(&w5[(size_t)(3 + j) * 384 + m]);
        g_scratch[OFF_B5 + m] = acc;
    }
}

// ---------------------------------------------------------------------------
// Farthest point sampling (redux.sync; first-occurrence argmax semantics).
// FL1: after sampling, the block computes conf + layer-1 (h1, fp16) for its
// own npoint rows.
// ---------------------------------------------------------------------------
template <int BDIM, int PT, bool FL1>
__global__ void fps_kernel(const float* __restrict__ pts_ext, long long pts_off,
                           int n, int npoint, int idx_off, long long nx_off,
                           const float* __restrict__ cw1, const float* __restrict__ cb1,
                           const float* __restrict__ cw2, const float* __restrict__ cb2,
                           const float* __restrict__ w1, const float* __restrict__ b1)
{
    extern __shared__ float sh[];
    float* spx = sh;
    float* spy = sh + n;
    float* spz = sh + 2 * n;
    uint32_t* sd  = (uint32_t*)(sh + 3 * n);   // [2][32] dist bits
    uint32_t* si  = sd + 64;                   // [2][32] idx
    int*      sidx  = (int*)(si + 64);         // [npoint] sampled indices
    float*    sconf = (float*)(sidx + ((npoint + 1) & ~1));

    const float* pts = (pts_off >= 0) ? (g_scratch + pts_off) : pts_ext;
    int b = blockIdx.x;
    pts += (size_t)b * n * 3;
    int tid = threadIdx.x, lane = tid & 31;
    int wid = tid >> 5;
    constexpr int NW = BDIM / 32;

    float px[PT], py[PT], pz[PT], dist[PT];
    {
        int t = 0;
        for (int i = tid; i < n; i += BDIM, t++) {
            float a = pts[3 * i], bb = pts[3 * i + 1], cc = pts[3 * i + 2];
            spx[i] = a; spy[i] = bb; spz[i] = cc;
            px[t] = a; py[t] = bb; pz[t] = cc; dist[t] = 1e10f;
        }
    }
    __syncthreads();

    int far = 0;
    for (int s = 0; s < npoint; s++) {
        if (tid == 0) {
            g_idx[idx_off + b * npoint + s] = far;
            if (FL1) sidx[s] = far;
            if (nx_off >= 0) {
                float* o = g_scratch + nx_off + ((size_t)b * npoint + s) * 3;
                o[0] = spx[far]; o[1] = spy[far]; o[2] = spz[far];
            }
        }
        float cx = spx[far], cy = spy[far], cz = spz[far];

        float bestd = -1.f; uint32_t besti = 0x7fffffffu;
#pragma unroll
        for (int t = 0; t < PT; t++) {
            int gi = tid + t * BDIM;
            if (gi < n) {
                float dx = px[t] - cx, dy = py[t] - cy, dz = pz[t] - cz;
                float d = dx * dx + dy * dy + dz * dz;
                if (d < dist[t]) dist[t] = d;
                if (dist[t] > bestd) { bestd = dist[t]; besti = gi; }
            }
        }
        uint32_t db = (bestd < 0.f) ? 0u : __float_as_uint(bestd);
        uint32_t wmax = redux_max(db);
        uint32_t wi = redux_min((db == wmax) ? besti : 0x7fffffffu);

        int par = (s & 1) * 32;
        if (lane == 0) { sd[par + wid] = wmax; si[par + wid] = wi; }
        __syncthreads();
        uint32_t dd = (lane < NW) ? sd[par + lane] : 0u;
        uint32_t ii = (lane < NW) ? si[par + lane] : 0x7fffffffu;
        uint32_t m2 = redux_max(dd);
        far = (int)redux_min((dd == m2) ? ii : 0x7fffffffu);
    }

    if (FL1) {
        __syncthreads();
        for (int s = tid; s < npoint; s += BDIM) {
            int idx = sidx[s];
            float x0 = spx[idx], x1 = spy[idx], x2 = spz[idx];
            float acc = 0.f;
#pragma unroll 8
            for (int j = 0; j < 64; j++) {
                float h = cb1[j] + x0 * cw1[j] + x1 * cw1[64 + j] + x2 * cw1[128 + j];
                h = fmaxf(h, 0.f);
                acc += h * cw2[j];
            }
            sconf[s] = 1.f / (1.f + expf(-(acc + cb2[0])));
        }
        __syncthreads();
        for (int e = tid; e < npoint * 16; e += BDIM) {
            int s = e >> 4, q = (e & 15) * 4;
            int idx = sidx[s];
            float a0 = sconf[s];
            float a1 = spx[idx], a2 = spy[idx], a3 = spz[idx];
            float o[4];
#pragma unroll
            for (int j = 0; j < 4; j++) {
                float v = b1[q + j];
                v += a0 * __ldg(&w1[0 * 64 + q + j]);
                v += a1 * __ldg(&w1[1 * 64 + q + j]);
                v += a2 * __ldg(&w1[2 * 64 + q + j]);
                v += a3 * __ldg(&w1[3 * 64 + q + j]);
                o[j] = fmaxf(v, 0.f);
            }
            __half2 p0 = __floats2half2_rn(o[0], o[1]);
            __half2 p1 = __floats2half2_rn(o[2], o[3]);
            uint2 pk = make_uint2(*(uint32_t*)&p0, *(uint32_t*)&p1);
            *(uint2*)(g_hbuf + HOFF_H1 + ((size_t)b * npoint + s) * 64 + q) = pk;
        }
    }
}

// ---------------------------------------------------------------------------
// fp16 HMMA GEMM: R12 core — K-chunk 32, FOUR buffers (80KB, 2 CTA/SM),
// single __syncthreads per chunk, cp.async lookahead 2. Epilogues:
//  flags bit0 = relu; bias_off >= 0 -> fp32 bias from g_scratch
//  wx != nullptr: rank-3 xyz correction; outmax: fused atomic max-pool
// ---------------------------------------------------------------------------
constexpr int LDW = 20;                       // words per smem row (16 + pad)
constexpr int TILE_W = 128 * LDW;
constexpr int TILE_B = TILE_W * 4;            // 10240 bytes
constexpr int TG_SMEM = 8 * TILE_B;           // 81920 bytes (4 buffers x A,B)

__global__ void __launch_bounds__(256)
tgemm_kernel(long long hoffA, int lda, long long hoffW, const float* __restrict__ bias,
             long long bias_off, long long offC, int ldc, int M, int N, int Kpad,
             int flags, int idx_off, int Sdst, int Ssrc,
             long long xoff, const float* __restrict__ wx, float* outmax)
{
    extern __shared__ uint32_t sm[];
    const __half* Wh = g_hbuf + hoffW;

    int tid = threadIdx.x, lane = tid & 31, wid = tid >> 5;
    int m0 = blockIdx.x * 128, n0 = blockIdx.y * 128;
    int wm = (wid >> 1) * 32, wn = (wid & 1) * 64;
    int g = lane >> 2, tg = lane & 3;

    float acc[2][8][4];
#pragma unroll
    for (int i = 0; i < 2; i++)
#pragma unroll
        for (int j = 0; j < 8; j++)
#pragma unroll
            for (int q = 0; q < 4; q++) acc[i][j][q] = 0.f;

    uint32_t sbase = smem_u32(sm);
    int nch = Kpad >> 5;

    int row0 = tid >> 2, cw = tid & 3;
    const __half* aptr[2];
    const __half* bptr[2];
    uint32_t soff[2];
#pragma unroll
    for (int j = 0; j < 2; j++) {
        int rloc = row0 + 64 * j;
        int rg = m0 + rloc;
        if (rg > M - 1) rg = M - 1;
        size_t srow;
        if (idx_off >= 0) {
            int bb = rg / Sdst;
            srow = (size_t)bb * Ssrc + g_idx[idx_off + rg];
        } else {
            srow = rg;
        }
        aptr[j] = g_hbuf + hoffA + srow * lda + cw * 8;
        bptr[j] = Wh + (size_t)(n0 + rloc) * Kpad + cw * 8;
        soff[j] = (rloc * LDW + cw * 4) << 2;
    }

#define TG_ISSUE(c)                                                   \
    do {                                                              \
        if ((c) < nch) {                                              \
            uint32_t aw = sbase + ((c) & 3) * 2 * TILE_B;             \
            uint32_t bw = aw + TILE_B;                                \
            int k0h = (c) * 32;                                       \
            _Pragma("unroll")                                         \
            for (int j = 0; j < 2; j++) {                             \
                cpa16(aw + soff[j], aptr[j] + k0h);                   \
                cpa16(bw + soff[j], bptr[j] + k0h);                   \
            }                                                         \
        }                                                             \
        cpa_commit();                                                 \
    } while (0)

    TG_ISSUE(0);
    TG_ISSUE(1);
    TG_ISSUE(2);

    uint32_t aoff = (((wm + (lane & 15)) * LDW + ((lane >> 4) << 2)) << 2);
    uint32_t boff = (((wn + ((lane >> 4)) * 8 + (lane & 7)) * LDW +
                      (((lane >> 3) & 1) << 2)) << 2);

    for (int c = 0; c < nch; c++) {
        cpa_wait2();
        __syncthreads();
        uint32_t Ab = sbase + (c & 3) * 2 * TILE_B;
        uint32_t Bb = Ab + TILE_B;
#pragma unroll
        for (int ks = 0; ks < 2; ks++) {
            uint32_t af[2][4];
#pragma unroll
            for (int mt = 0; mt < 2; mt++)
                ldsm4(af[mt][0], af[mt][1], af[mt][2], af[mt][3],
                      Ab + aoff + mt * 16 * LDW * 4 + ks * 32);
            uint32_t bf[8][2];
#pragma unroll
            for (int np = 0; np < 4; np++)
                ldsm4(bf[2 * np][0], bf[2 * np][1], bf[2 * np + 1][0], bf[2 * np + 1][1],
                      Bb + boff + np * 16 * LDW * 4 + ks * 32);
#pragma unroll
            for (int mt = 0; mt < 2; mt++)
#pragma unroll
                for (int nt = 0; nt < 8; nt++)
                    mma16n8k16(acc[mt][nt], af[mt], bf[nt]);
        }
        TG_ISSUE(c + 3);
    }
#undef TG_ISSUE

    bool do_relu = flags & 1;
    const float* bptr_f = (bias_off >= 0) ? (g_scratch + bias_off) : bias;
    __half* Ch = g_hbuf + offC;
#pragma unroll
    for (int mt = 0; mt < 2; mt++) {
        int r0 = m0 + wm + mt * 16 + g;
        float nxa[3] = {0.f, 0.f, 0.f}, nxb[3] = {0.f, 0.f, 0.f};
        if (wx) {
            if (r0 < M) {
                const float* s = g_scratch + xoff + (size_t)r0 * 3;
                nxa[0] = s[0]; nxa[1] = s[1]; nxa[2] = s[2];
            }
            if (r0 + 8 < M) {
                const float* s = g_scratch + xoff + (size_t)(r0 + 8) * 3;
                nxb[0] = s[0]; nxb[1] = s[1]; nxb[2] = s[2];
            }
        }
#pragma unroll
        for (int nt = 0; nt < 8; nt++) {
            int col = n0 + wn + nt * 8 + 2 * tg;
            float bz0 = bptr_f[col], bz1 = bptr_f[col + 1];
            float v0 = acc[mt][nt][0] + bz0, v1 = acc[mt][nt][1] + bz1;
            float v2 = acc[mt][nt][2] + bz0, v3 = acc[mt][nt][3] + bz1;
            if (wx) {
#pragma unroll
                for (int i = 0; i < 3; i++) {
                    float w0 = __ldg(&wx[(size_t)i * N + col]);
                    float w1v = __ldg(&wx[(size_t)i * N + col + 1]);
                    v0 += nxa[i] * w0; v1 += nxa[i] * w1v;
                    v2 += nxb[i] * w0; v3 += nxb[i] * w1v;
                }
            }
            if (do_relu) {
                v0 = fmaxf(v0, 0.f); v1 = fmaxf(v1, 0.f);
                v2 = fmaxf(v2, 0.f); v3 = fmaxf(v3, 0.f);
            }
            if (outmax) {
                if (r0 < M) {
                    int ob = (r0 / Sdst) << 9;
                    atomicMax((int*)&outmax[ob + col], __float_as_int(v0));
                    atomicMax((int*)&outmax[ob + col + 1], __float_as_int(v1));
                }
                if (r0 + 8 < M) {
                    int ob = ((r0 + 8) / Sdst) << 9;
                    atomicMax((int*)&outmax[ob + col], __float_as_int(v2));
                    atomicMax((int*)&outmax[ob + col + 1], __float_as_int(v3));
                }
            } else {
                __half2 pa = __floats2half2_rn(v0, v1);
                __half2 pb = __floats2half2_rn(v2, v3);
                if (r0 < M)     *(__half2*)(Ch + (size_t)r0 * ldc + col) = pa;
                if (r0 + 8 < M) *(__half2*)(Ch + (size_t)(r0 + 8) * ldc + col) = pb;
            }
        }
    }
}

// ---------------------------------------------------------------------------
// Launch
// ---------------------------------------------------------------------------
constexpr int FPS1_SMEM = 3 * NPTS * 4 + 512 + S1 * 8 + 64;

extern "C" void kernel_launch(void* const* d_in, const int* in_sizes, int n_in,
                              void* d_out, int out_size)
{
    const float* x    = (const float*)d_in[0];
    const float* cw1  = (const float*)d_in[1];
    const float* cb1  = (const float*)d_in[2];
    const float* cw2  = (const float*)d_in[3];
    const float* cb2  = (const float*)d_in[4];
    const float* w1   = (const float*)d_in[5];
    const float* b1   = (const float*)d_in[6];
    const float* w2   = (const float*)d_in[7];
    const float* b2   = (const float*)d_in[8];
    const float* w3   = (const float*)d_in[9];
    const float* b3   = (const float*)d_in[10];
    const float* w4   = (const float*)d_in[11];
    const float* b4   = (const float*)d_in[12];
    const float* w5   = (const float*)d_in[13];
    const float* b5   = (const float*)d_in[14];
    const float* w6   = (const float*)d_in[15];
    const float* b6   = (const float*)d_in[16];
    const float* pc1w = (const float*)d_in[17];
    const float* pc1b = (const float*)d_in[18];
    const float* pc2w = (const float*)d_in[19];
    const float* pc2b = (const float*)d_in[20];

    float* out  = (float*)d_out;            // (B,512)
    float* conf = out + BATCH * 512;        // (B,N,1)

    static cudaStream_t s1 = nullptr;
    static cudaEvent_t evFork, evF1, evF2, evF3;
    if (!s1) {
        cudaStreamCreateWithFlags(&s1, cudaStreamNonBlocking);
        cudaEventCreateWithFlags(&evFork, cudaEventDisableTiming);
        cudaEventCreateWithFlags(&evF1, cudaEventDisableTiming);
        cudaEventCreateWithFlags(&evF2, cudaEventDisableTiming);
        cudaEventCreateWithFlags(&evF3, cudaEventDisableTiming);
        cudaFuncSetAttribute(tgemm_kernel, cudaFuncAttributeMaxDynamicSharedMemorySize,
                             TG_SMEM);
        cudaFuncSetAttribute(fps_kernel<1024, 4, true>,
                             cudaFuncAttributeMaxDynamicSharedMemorySize, FPS1_SMEM);
    }

    cudaEventRecord(evFork, 0);
    cudaStreamWaitEvent(s1, evFork, 0);
    fps_kernel<1024, 4, true><<<BATCH, 1024, FPS1_SMEM, s1>>>(
        x, -1LL, NPTS, S1, IDX1, (long long)OFF_NX1, cw1, cb1, cw2, cb2, w1, b1);
    cudaEventRecord(evF1, s1);
    fps_kernel<256, 2, false><<<BATCH, 256, 3 * S1 * 4 + 1024, s1>>>(
        nullptr, (long long)OFF_NX1, S1, S2, IDX2, (long long)OFF_NX2,
        nullptr, nullptr, nullptr, nullptr, nullptr, nullptr);
    cudaEventRecord(evF2, s1);
    fps_kernel<128, 2, false><<<BATCH, 128, 3 * S2 * 4 + 1024, s1>>>(
        nullptr, (long long)OFF_NX2, S2, S3, IDX3, -1LL,
        nullptr, nullptr, nullptr, nullptr, nullptr, nullptr);
    cudaEventRecord(evF3, s1);

    // Weight prep + conf (+ out zeroing), hidden under fps1 on the main stream
    wconv_kernel<<<(WCONV_TOTAL + 255) / 256, 256>>>(w2, w4, w6);
    wprod_kernel<<<(256 * 256 + 255) / 256, 256>>>(WC_W3C, pc1w, w3, 256, 256, 256);
    wprod_kernel<<<(384 * 384 + 255) / 256, 256>>>(WC_W5C, pc2w, w5, 384, 384, 384);
    wbias_kernel<<<3, 256>>>(pc1b, w3, b3, pc2b, w5, b5);
    conf_kernel<<<(BATCH * NPTS + 255) / 256, 256>>>(x, cw1, cb1, cw2, cb2, conf, out);

    cudaStreamWaitEvent(0, evF1, 0);

    // h1 @ w2 -> l2g
    tgemm_kernel<<<dim3(M1 / 128, 2), 256, TG_SMEM>>>(
        (long long)HOFF_H1, 64, (long long)(HOFF_WC + WC_W2), b2, -1LL,
        (long long)HOFF_L2G, 256, M1, 256, 64, 1, -1, 0, 0, -1LL, nullptr, nullptr);
    // l2g @ (pc1w∘w3) + nx1·w3[0:3] + b3' -> l4
    tgemm_kernel<<<dim3(M1 / 128, 2), 256, TG_SMEM>>>(
        (long long)HOFF_L2G, 256, (long long)(HOFF_WC + WC_W3C), nullptr, (long long)OFF_B3,
        (long long)HOFF_L4, 256, M1, 256, 256, 1, -1, 0, 0,
        (long long)OFF_NX1, w3, nullptr);
    // l4 @ w4 -> l5
    tgemm_kernel<<<dim3(M1 / 128, 3), 256, TG_SMEM>>>(
        (long long)HOFF_L4, 256, (long long)(HOFF_WC + WC_W4), b4, -1LL,
        (long long)HOFF_L5, 384, M1, 384, 256, 1, -1, 0, 0, -1LL, nullptr, nullptr);

    cudaStreamWaitEvent(0, evF2, 0);
    // gather(l5, idx2) @ (pc2w∘w5) + nx2·w5[0:3] + b5' -> l7
    tgemm_kernel<<<dim3(M2 / 128, 3), 256, TG_SMEM>>>(
        (long long)HOFF_L5, 384, (long long)(HOFF_WC + WC_W5C), nullptr, (long long)OFF_B5,
        (long long)HOFF_L7, 384, M2, 384, 384, 1, IDX2, S2, S1,
        (long long)OFF_NX2, w5, nullptr);

    cudaStreamWaitEvent(0, evF3, 0);
    // gather(l7, idx3) @ w6 -> relu -> fused atomic max-pool into out
    tgemm_kernel<<<dim3((M3 + 127) / 128, 4), 256, TG_SMEM>>>(
        (long long)HOFF_L7, 384, (long long)(HOFF_WC + WC_W6), b6, -1LL,
        0LL, 512, M3, 512, 384, 1, IDX3, S3, S2, -1LL, nullptr, out);
}

// round 16
// speedup vs baseline: 1.1053x; 1.1053x over previous
#include <cuda_runtime.h>
#include <cuda_fp16.h>
#include <math.h>
#include <cstdint>

// ---------------------------------------------------------------------------
// Problem constants
// ---------------------------------------------------------------------------
#define BATCH 64
#define NPTS  4096

constexpr int S1 = 500, S2 = 250, S3 = 125;
constexpr int M1 = BATCH * S1;   // 32000
constexpr int M2 = BATCH * S2;   // 16000
constexpr int M3 = BATCH * S3;   // 8000

// ---------------------------------------------------------------------------
// Float scratch: sampled coords + composed biases
// ---------------------------------------------------------------------------
constexpr size_t OFF_NX1 = 0;                          // [M1,3]
constexpr size_t OFF_NX2 = OFF_NX1 + (size_t)M1 * 3;   // [M2,3]
constexpr size_t OFF_B3  = OFF_NX2 + (size_t)M2 * 3;   // [256]
constexpr size_t OFF_B5  = OFF_B3 + 256;               // [384]
constexpr size_t SCRATCH_SZ = OFF_B5 + 384;

// ---------------------------------------------------------------------------
// Half buffer: activations + fp16 weights [N][Kpad] (zero-padded).
// ---------------------------------------------------------------------------
constexpr size_t HOFF_L2G = 0;                              // [M1,256]
constexpr size_t HOFF_L4  = HOFF_L2G + (size_t)M1 * 256;    // [M1,256]
constexpr size_t HOFF_L5  = HOFF_L4  + (size_t)M1 * 256;    // [M1,384]
constexpr size_t HOFF_L7  = HOFF_L5  + (size_t)M1 * 384;    // [M2,384]
constexpr size_t HOFF_WC  = HOFF_L7  + (size_t)M2 * 384;
constexpr int WC_W2  = 0;        // Kpad  64, N 256
constexpr int WC_W3C = 16384;    // Kpad 256, N 256  (pc1w @ w3[3:259])
constexpr int WC_W4  = 81920;    // Kpad 256, N 384
constexpr int WC_W5C = 180224;   // Kpad 384, N 384  (pc2w @ w5[3:387])
constexpr int WC_W6  = 327680;   // Kpad 384, N 512
constexpr int WC_TOTAL = 524288;
constexpr int WCONV_TOTAL = 16384 + 98304 + 196608;  // w2 + w4 + w6
constexpr size_t HBUF_SZ = HOFF_WC + WC_TOTAL;

__device__ __align__(256) float  g_scratch[SCRATCH_SZ];
__device__ __align__(256) __half g_hbuf[HBUF_SZ];
__device__ int g_idx[M1 + M2 + M3];
constexpr int IDX1 = 0, IDX2 = M1, IDX3 = M1 + M2;

// ---------------------------------------------------------------------------
// PTX helpers
// ---------------------------------------------------------------------------
__device__ __forceinline__ void mma16n8k16(float* c, const uint32_t* a, const uint32_t* b) {
    asm volatile(
        "mma.sync.aligned.m16n8k16.row.col.f32.f16.f16.f32 "
        "{%0,%1,%2,%3}, {%4,%5,%6,%7}, {%8,%9}, {%0,%1,%2,%3};"
        : "+f"(c[0]), "+f"(c[1]), "+f"(c[2]), "+f"(c[3])
        : "r"(a[0]), "r"(a[1]), "r"(a[2]), "r"(a[3]), "r"(b[0]), "r"(b[1]));
}
__device__ __forceinline__ void ldsm4(uint32_t& r0, uint32_t& r1, uint32_t& r2,
                                      uint32_t& r3, uint32_t addr) {
    asm volatile("ldmatrix.sync.aligned.m8n8.x4.shared.b16 {%0,%1,%2,%3}, [%4];"
                 : "=r"(r0), "=r"(r1), "=r"(r2), "=r"(r3) : "r"(addr));
}
__device__ __forceinline__ uint32_t smem_u32(const void* p) {
    uint32_t a;
    asm("{ .reg .u64 t; cvta.to.shared.u64 t, %1; cvt.u32.u64 %0, t; }"
        : "=r"(a) : "l"(p));
    return a;
}
__device__ __forceinline__ void cpa16(uint32_t dst, const __half* src) {
    asm volatile("cp.async.ca.shared.global [%0], [%1], 16;"
                 :: "r"(dst), "l"(src) : "memory");
}
__device__ __forceinline__ void cpa_commit() {
    asm volatile("cp.async.commit_group;" ::: "memory");
}
__device__ __forceinline__ void cpa_wait2() {
    asm volatile("cp.async.wait_group 2;" ::: "memory");
}
__device__ __forceinline__ uint32_t redux_max(uint32_t v) {
    uint32_t r;
    asm volatile("redux.sync.max.u32 %0, %1, 0xffffffff;" : "=r"(r) : "r"(v));
    return r;
}
__device__ __forceinline__ uint32_t redux_min(uint32_t v) {
    uint32_t r;
    asm volatile("redux.sync.min.u32 %0, %1, 0xffffffff;" : "=r"(r) : "r"(v));
    return r;
}

// ---------------------------------------------------------------------------
// Confidence MLP (all points) + zero-init of the (B,512) max-pool output
// ---------------------------------------------------------------------------
__global__ void conf_kernel(const float* __restrict__ x,
                            const float* __restrict__ cw1,
                            const float* __restrict__ cb1,
                            const float* __restrict__ cw2,
                            const float* __restrict__ cb2,
                            float* __restrict__ conf,
                            float* __restrict__ outz)
{
    int p = blockIdx.x * blockDim.x + threadIdx.x;
    if (p < BATCH * 512) outz[p] = 0.f;
    if (p >= BATCH * NPTS) return;
    float x0 = x[3 * p], x1 = x[3 * p + 1], x2 = x[3 * p + 2];
    float acc = 0.f;
#pragma unroll 8
    for (int j = 0; j < 64; j++) {
        float h = cb1[j] + x0 * cw1[j] + x1 * cw1[64 + j] + x2 * cw1[128 + j];
        h = fmaxf(h, 0.f);
        acc += h * cw2[j];
    }
    float z = acc + cb2[0];
    conf[p] = 1.f / (1.f + expf(-z));
}

// ---------------------------------------------------------------------------
// Plain weight transposes -> fp16 [N][Kpad] (w2, w4, w6)
// ---------------------------------------------------------------------------
__global__ void wconv_kernel(const float* __restrict__ w2, const float* __restrict__ w4,
                             const float* __restrict__ w6)
{
    int e = blockIdx.x * blockDim.x + threadIdx.x;
    if (e >= WCONV_TOTAL) return;
    const float* src; int base, N, K, local;
    if (e < 16384)       { src = w2; base = WC_W2; N = 256; K = 64;  local = e; }
    else if (e < 114688) { src = w4; base = WC_W4; N = 384; K = 256; local = e - 16384; }
    else                 { src = w6; base = WC_W6; N = 512; K = 384; local = e - 114688; }
    int n = local / K, k = local - n * K;
    g_hbuf[HOFF_WC + base + (size_t)n * K + k] =
        __float2half_rn(__ldg(&src[(size_t)k * N + n]));
}

// ---------------------------------------------------------------------------
// Composed weight products: Wc[n][k] = sum_j pw[k][j] * w[(3+j)*N + n]
// ---------------------------------------------------------------------------
__global__ void wprod_kernel(int out_base, const float* __restrict__ pw,
                             const float* __restrict__ w, int N, int J, int K)
{
    int e = blockIdx.x * blockDim.x + threadIdx.x;
    if (e >= N * K) return;
    int n = e % N, k = e / N;
    const float* pwr = pw + (size_t)k * J;
    float acc = 0.f;
#pragma unroll 4
    for (int j = 0; j < J; j++)
        acc += __ldg(&pwr[j]) * __ldg(&w[(size_t)(3 + j) * N + n]);
    g_hbuf[HOFF_WC + out_base + (size_t)n * K + k] = __float2half_rn(acc);
}

// Composed biases: b' = b + pb @ w[3:,:]
__global__ void wbias_kernel(const float* __restrict__ pc1b, const float* __restrict__ w3,
                             const float* __restrict__ b3,
                             const float* __restrict__ pc2b, const float* __restrict__ w5,
                             const float* __restrict__ b5)
{
    int n = blockIdx.x * blockDim.x + threadIdx.x;
    if (n < 256) {
        float acc = b3[n];
        for (int j = 0; j < 256; j++) acc += pc1b[j] * __ldg(&w3[(size_t)(3 + j) * 256 + n]);
        g_scratch[OFF_B3 + n] = acc;
    } else if (n < 640) {
        int m = n - 256;
        float acc = b5[m];
        for (int j = 0; j < 384; j++) acc += pc2b[j] * __ldg(&w5[(size_t)(3 + j) * 384 + m]);
        g_scratch[OFF_B5 + m] = acc;
    }
}

// ---------------------------------------------------------------------------
// Farthest point sampling (redux.sync; first-occurrence argmax semantics)
// ---------------------------------------------------------------------------
template <int BDIM, int PT>
__global__ void fps_kernel(const float* __restrict__ pts_ext, long long pts_off,
                           int n, int npoint, int idx_off, long long nx_off)
{
    extern __shared__ float sh[];
    float* spx = sh;
    float* spy = sh + n;
    float* spz = sh + 2 * n;
    uint32_t* sd = (uint32_t*)(sh + 3 * n);
    uint32_t* si = sd + 64;

    const float* pts = (pts_off >= 0) ? (g_scratch + pts_off) : pts_ext;
    int b = blockIdx.x;
    pts += (size_t)b * n * 3;
    int tid = threadIdx.x, lane = tid & 31;
    int wid = tid >> 5;
    constexpr int NW = BDIM / 32;

    float px[PT], py[PT], pz[PT], dist[PT];
    {
        int t = 0;
        for (int i = tid; i < n; i += BDIM, t++) {
            float a = pts[3 * i], bb = pts[3 * i + 1], cc = pts[3 * i + 2];
            spx[i] = a; spy[i] = bb; spz[i] = cc;
            px[t] = a; py[t] = bb; pz[t] = cc; dist[t] = 1e10f;
        }
    }
    __syncthreads();

    int far = 0;
    for (int s = 0; s < npoint; s++) {
        if (tid == 0) {
            g_idx[idx_off + b * npoint + s] = far;
            if (nx_off >= 0) {
                float* o = g_scratch + nx_off + ((size_t)b * npoint + s) * 3;
                o[0] = spx[far]; o[1] = spy[far]; o[2] = spz[far];
            }
        }
        float cx = spx[far], cy = spy[far], cz = spz[far];

        float bestd = -1.f; uint32_t besti = 0x7fffffffu;
#pragma unroll
        for (int t = 0; t < PT; t++) {
            int gi = tid + t * BDIM;
            if (gi < n) {
                float dx = px[t] - cx, dy = py[t] - cy, dz = pz[t] - cz;
                float d = dx * dx + dy * dy + dz * dz;
                if (d < dist[t]) dist[t] = d;
                if (dist[t] > bestd) { bestd = dist[t]; besti = gi; }
            }
        }
        uint32_t db = (bestd < 0.f) ? 0u : __float_as_uint(bestd);
        uint32_t wmax = redux_max(db);
        uint32_t wi = redux_min((db == wmax) ? besti : 0x7fffffffu);

        int par = (s & 1) * 32;
        if (lane == 0) { sd[par + wid] = wmax; si[par + wid] = wi; }
        __syncthreads();
        uint32_t dd = (lane < NW) ? sd[par + lane] : 0u;
        uint32_t ii = (lane < NW) ? si[par + lane] : 0x7fffffffu;
        uint32_t m2 = redux_max(dd);
        far = (int)redux_min((dd == m2) ? ii : 0x7fffffffu);
    }
}

// ---------------------------------------------------------------------------
// fp16 HMMA GEMM: R12/R13 core — K-chunk 32, FOUR buffers (80KB, 2 CTA/SM),
// single __syncthreads per chunk, cp.async lookahead 2.
//  flags bit0 = relu; bit2 = A computed on-the-fly as layer1 output:
//    h1[q] = relu(b1[q] + conf*w1[q] + x·w1[64/128/192 + q]) (fp32 -> fp16),
//    stored synchronously to the operand smem buffer (barrier-ordered).
//  bias_off >= 0 -> fp32 bias from g_scratch; wx: rank-3 xyz correction;
//  outmax: fused atomic max-pool; else half2 store to g_hbuf + offC.
// ---------------------------------------------------------------------------
constexpr int LDW = 20;                       // words per smem row (16 + pad)
constexpr int TILE_W = 128 * LDW;
constexpr int TILE_B = TILE_W * 4;            // 10240 bytes
constexpr int TG_SMEM = 8 * TILE_B;           // 81920 bytes (4 buffers x A,B)

__global__ void __launch_bounds__(256)
tgemm_kernel(long long hoffA, int lda, long long hoffW, const float* __restrict__ bias,
             long long bias_off, long long offC, int ldc, int M, int N, int Kpad,
             int flags, int idx_off, int Sdst, int Ssrc,
             long long xoff, const float* __restrict__ wx, float* outmax,
             const float* __restrict__ xin, const float* __restrict__ confin,
             const float* __restrict__ w1p, const float* __restrict__ b1p)
{
    extern __shared__ uint32_t sm[];
    const __half* Wh = g_hbuf + hoffW;

    int tid = threadIdx.x, lane = tid & 31, wid = tid >> 5;
    int m0 = blockIdx.x * 128, n0 = blockIdx.y * 128;
    int wm = (wid >> 1) * 32, wn = (wid & 1) * 64;
    int g = lane >> 2, tg = lane & 3;
    bool cmode = flags & 4;

    float acc[2][8][4];
#pragma unroll
    for (int i = 0; i < 2; i++)
#pragma unroll
        for (int j = 0; j < 8; j++)
#pragma unroll
            for (int q = 0; q < 4; q++) acc[i][j][q] = 0.f;

    uint32_t sbase = smem_u32(sm);
    int nch = Kpad >> 5;

    int row0 = tid >> 2, cw = tid & 3;
    const __half* aptr[2];
    const __half* bptr[2];
    uint32_t soff[2];
    float av[2][4];
#pragma unroll
    for (int j = 0; j < 2; j++) {
        int rloc = row0 + 64 * j;
        int rg = m0 + rloc;
        if (rg > M - 1) rg = M - 1;
        size_t srow;
        if (idx_off >= 0) {
            int bb = rg / Sdst;
            srow = (size_t)bb * Ssrc + g_idx[idx_off + rg];
        } else {
            srow = rg;
        }
        if (cmode) {
            // srow == b*NPTS + idx (Ssrc = NPTS): point base in x/conf
            av[j][0] = confin[srow];
            av[j][1] = xin[3 * srow];
            av[j][2] = xin[3 * srow + 1];
            av[j][3] = xin[3 * srow + 2];
            aptr[j] = nullptr;
        } else {
            aptr[j] = g_hbuf + hoffA + srow * lda + cw * 8;
        }
        bptr[j] = Wh + (size_t)(n0 + rloc) * Kpad + cw * 8;
        soff[j] = (rloc * LDW + cw * 4) << 2;
    }

#define TG_ISSUE(c)                                                          \
    do {                                                                     \
        if ((c) < nch) {                                                     \
            uint32_t bufofs = ((c) & 3) * 2 * TILE_B;                        \
            uint32_t aw = sbase + bufofs;                                    \
            uint32_t bw = aw + TILE_B;                                       \
            int k0h = (c) * 32;                                              \
            if (cmode) {                                                     \
                _Pragma("unroll")                                            \
                for (int j = 0; j < 2; j++) {                                \
                    int qb = k0h + cw * 8;                                   \
                    float hv[8];                                             \
                    _Pragma("unroll")                                        \
                    for (int t = 0; t < 8; t++) {                            \
                        int q = qb + t;                                      \
                        float v = __ldg(&b1p[q]);                            \
                        v += av[j][0] * __ldg(&w1p[q]);                      \
                        v += av[j][1] * __ldg(&w1p[64 + q]);                 \
                        v += av[j][2] * __ldg(&w1p[128 + q]);                \
                        v += av[j][3] * __ldg(&w1p[192 + q]);                \
                        hv[t] = fmaxf(v, 0.f);                               \
                    }                                                        \
                    __half2 h0 = __floats2half2_rn(hv[0], hv[1]);            \
                    __half2 h1 = __floats2half2_rn(hv[2], hv[3]);            \
                    __half2 h2 = __floats2half2_rn(hv[4], hv[5]);            \
                    __half2 h3 = __floats2half2_rn(hv[6], hv[7]);            \
                    uint4 pk = make_uint4(*(uint32_t*)&h0, *(uint32_t*)&h1,  \
                                          *(uint32_t*)&h2, *(uint32_t*)&h3); \
                    *(uint4*)((char*)sm + bufofs + soff[j]) = pk;            \
                }                                                            \
            } else {                                                         \
                _Pragma("unroll")                                            \
                for (int j = 0; j < 2; j++)                                  \
                    cpa16(aw + soff[j], aptr[j] + k0h);                      \
            }                                                                \
            _Pragma("unroll")                                                \
            for (int j = 0; j < 2; j++)                                      \
                cpa16(bw + soff[j], bptr[j] + k0h);                          \
        }                                                                    \
        cpa_commit();                                                        \
    } while (0)

    TG_ISSUE(0);
    TG_ISSUE(1);
    TG_ISSUE(2);

    uint32_t aoff = (((wm + (lane & 15)) * LDW + ((lane >> 4) << 2)) << 2);
    uint32_t boff = (((wn + ((lane >> 4)) * 8 + (lane & 7)) * LDW +
                      (((lane >> 3) & 1) << 2)) << 2);

    for (int c = 0; c < nch; c++) {
        cpa_wait2();
        __syncthreads();
        uint32_t Ab = sbase + (c & 3) * 2 * TILE_B;
        uint32_t Bb = Ab + TILE_B;
#pragma unroll
        for (int ks = 0; ks < 2; ks++) {
            uint32_t af[2][4];
#pragma unroll
            for (int mt = 0; mt < 2; mt++)
                ldsm4(af[mt][0], af[mt][1], af[mt][2], af[mt][3],
                      Ab + aoff + mt * 16 * LDW * 4 + ks * 32);
            uint32_t bf[8][2];
#pragma unroll
            for (int np = 0; np < 4; np++)
                ldsm4(bf[2 * np][0], bf[2 * np][1], bf[2 * np + 1][0], bf[2 * np + 1][1],
                      Bb + boff + np * 16 * LDW * 4 + ks * 32);
#pragma unroll
            for (int mt = 0; mt < 2; mt++)
#pragma unroll
                for (int nt = 0; nt < 8; nt++)
                    mma16n8k16(acc[mt][nt], af[mt], bf[nt]);
        }
        TG_ISSUE(c + 3);
    }
#undef TG_ISSUE

    bool do_relu = flags & 1;
    const float* bptr_f = (bias_off >= 0) ? (g_scratch + bias_off) : bias;
    __half* Ch = g_hbuf + offC;
#pragma unroll
    for (int mt = 0; mt < 2; mt++) {
        int r0 = m0 + wm + mt * 16 + g;
        float nxa[3] = {0.f, 0.f, 0.f}, nxb[3] = {0.f, 0.f, 0.f};
        if (wx) {
            if (r0 < M) {
                const float* s = g_scratch + xoff + (size_t)r0 * 3;
                nxa[0] = s[0]; nxa[1] = s[1]; nxa[2] = s[2];
            }
            if (r0 + 8 < M) {
                const float* s = g_scratch + xoff + (size_t)(r0 + 8) * 3;
                nxb[0] = s[0]; nxb[1] = s[1]; nxb[2] = s[2];
            }
        }
#pragma unroll
        for (int nt = 0; nt < 8; nt++) {
            int col = n0 + wn + nt * 8 + 2 * tg;
            float bz0 = bptr_f[col], bz1 = bptr_f[col + 1];
            float v0 = acc[mt][nt][0] + bz0, v1 = acc[mt][nt][1] + bz1;
            float v2 = acc[mt][nt][2] + bz0, v3 = acc[mt][nt][3] + bz1;
            if (wx) {
#pragma unroll
                for (int i = 0; i < 3; i++) {
                    float w0 = __ldg(&wx[(size_t)i * N + col]);
                    float w1v = __ldg(&wx[(size_t)i * N + col + 1]);
                    v0 += nxa[i] * w0; v1 += nxa[i] * w1v;
                    v2 += nxb[i] * w0; v3 += nxb[i] * w1v;
                }
            }
            if (do_relu) {
                v0 = fmaxf(v0, 0.f); v1 = fmaxf(v1, 0.f);
                v2 = fmaxf(v2, 0.f); v3 = fmaxf(v3, 0.f);
            }
            if (outmax) {
                if (r0 < M) {
                    int ob = (r0 / Sdst) << 9;
                    atomicMax((int*)&outmax[ob + col], __float_as_int(v0));
                    atomicMax((int*)&outmax[ob + col + 1], __float_as_int(v1));
                }
                if (r0 + 8 < M) {
                    int ob = ((r0 + 8) / Sdst) << 9;
                    atomicMax((int*)&outmax[ob + col], __float_as_int(v2));
                    atomicMax((int*)&outmax[ob + col + 1], __float_as_int(v3));
                }
            } else {
                __half2 pa = __floats2half2_rn(v0, v1);
                __half2 pb = __floats2half2_rn(v2, v3);
                if (r0 < M)     *(__half2*)(Ch + (size_t)r0 * ldc + col) = pa;
                if (r0 + 8 < M) *(__half2*)(Ch + (size_t)(r0 + 8) * ldc + col) = pb;
            }
        }
    }
}

// ---------------------------------------------------------------------------
// Launch
// ---------------------------------------------------------------------------
extern "C" void kernel_launch(void* const* d_in, const int* in_sizes, int n_in,
                              void* d_out, int out_size)
{
    const float* x    = (const float*)d_in[0];
    const float* cw1  = (const float*)d_in[1];
    const float* cb1  = (const float*)d_in[2];
    const float* cw2  = (const float*)d_in[3];
    const float* cb2  = (const float*)d_in[4];
    const float* w1   = (const float*)d_in[5];
    const float* b1   = (const float*)d_in[6];
    const float* w2   = (const float*)d_in[7];
    const float* b2   = (const float*)d_in[8];
    const float* w3   = (const float*)d_in[9];
    const float* b3   = (const float*)d_in[10];
    const float* w4   = (const float*)d_in[11];
    const float* b4   = (const float*)d_in[12];
    const float* w5   = (const float*)d_in[13];
    const float* b5   = (const float*)d_in[14];
    const float* w6   = (const float*)d_in[15];
    const float* b6   = (const float*)d_in[16];
    const float* pc1w = (const float*)d_in[17];
    const float* pc1b = (const float*)d_in[18];
    const float* pc2w = (const float*)d_in[19];
    const float* pc2b = (const float*)d_in[20];

    float* out  = (float*)d_out;            // (B,512)
    float* conf = out + BATCH * 512;        // (B,N,1)

    static cudaStream_t s1 = nullptr;
    static cudaEvent_t evFork, evF1, evF2, evF3;
    if (!s1) {
        cudaStreamCreateWithFlags(&s1, cudaStreamNonBlocking);
        cudaEventCreateWithFlags(&evFork, cudaEventDisableTiming);
        cudaEventCreateWithFlags(&evF1, cudaEventDisableTiming);
        cudaEventCreateWithFlags(&evF2, cudaEventDisableTiming);
        cudaEventCreateWithFlags(&evF3, cudaEventDisableTiming);
        cudaFuncSetAttribute(tgemm_kernel, cudaFuncAttributeMaxDynamicSharedMemorySize,
                             TG_SMEM);
        cudaFuncSetAttribute(fps_kernel<1024, 4>,
                             cudaFuncAttributeMaxDynamicSharedMemorySize,
                             3 * NPTS * 4 + 1024);
    }

    cudaEventRecord(evFork, 0);
    cudaStreamWaitEvent(s1, evFork, 0);
    fps_kernel<1024, 4><<<BATCH, 1024, 3 * NPTS * 4 + 1024, s1>>>(
        x, -1LL, NPTS, S1, IDX1, (long long)OFF_NX1);
    cudaEventRecord(evF1, s1);
    fps_kernel<256, 2><<<BATCH, 256, 3 * S1 * 4 + 1024, s1>>>(
        nullptr, (long long)OFF_NX1, S1, S2, IDX2, (long long)OFF_NX2);
    cudaEventRecord(evF2, s1);
    fps_kernel<128, 2><<<BATCH, 128, 3 * S2 * 4 + 1024, s1>>>(
        nullptr, (long long)OFF_NX2, S2, S3, IDX3, -1LL);
    cudaEventRecord(evF3, s1);

    // Weight prep + conf (+ out zeroing), hidden under fps1 on the main stream
    wconv_kernel<<<(WCONV_TOTAL + 255) / 256, 256>>>(w2, w4, w6);
    wprod_kernel<<<(256 * 256 + 255) / 256, 256>>>(WC_W3C, pc1w, w3, 256, 256, 256);
    wprod_kernel<<<(384 * 384 + 255) / 256, 256>>>(WC_W5C, pc2w, w5, 384, 384, 384);
    wbias_kernel<<<3, 256>>>(pc1b, w3, b3, pc2b, w5, b5);
    conf_kernel<<<(BATCH * NPTS + 255) / 256, 256>>>(x, cw1, cb1, cw2, cb2, conf, out);

    cudaStreamWaitEvent(0, evF1, 0);

    // GEMM1: h1 (computed on the fly from conf/x via w1,b1) @ w2 -> l2g
    tgemm_kernel<<<dim3(M1 / 128, 2), 256, TG_SMEM>>>(
        0LL, 64, (long long)(HOFF_WC + WC_W2), b2, -1LL,
        (long long)HOFF_L2G, 256, M1, 256, 64, 1 | 4, IDX1, S1, NPTS,
        -1LL, nullptr, nullptr, x, conf, w1, b1);
    // l2g @ (pc1w∘w3) + nx1·w3[0:3] + b3' -> l4
    tgemm_kernel<<<dim3(M1 / 128, 2), 256, TG_SMEM>>>(
        (long long)HOFF_L2G, 256, (long long)(HOFF_WC + WC_W3C), nullptr, (long long)OFF_B3,
        (long long)HOFF_L4, 256, M1, 256, 256, 1, -1, 0, 0,
        (long long)OFF_NX1, w3, nullptr, nullptr, nullptr, nullptr, nullptr);
    // l4 @ w4 -> l5
    tgemm_kernel<<<dim3(M1 / 128, 3), 256, TG_SMEM>>>(
        (long long)HOFF_L4, 256, (long long)(HOFF_WC + WC_W4), b4, -1LL,
        (long long)HOFF_L5, 384, M1, 384, 256, 1, -1, 0, 0,
        -1LL, nullptr, nullptr, nullptr, nullptr, nullptr, nullptr);

    cudaStreamWaitEvent(0, evF2, 0);
    // gather(l5, idx2) @ (pc2w∘w5) + nx2·w5[0:3] + b5' -> l7
    tgemm_kernel<<<dim3(M2 / 128, 3), 256, TG_SMEM>>>(
        (long long)HOFF_L5, 384, (long long)(HOFF_WC + WC_W5C), nullptr, (long long)OFF_B5,
        (long long)HOFF_L7, 384, M2, 384, 384, 1, IDX2, S2, S1,
        (long long)OFF_NX2, w5, nullptr, nullptr, nullptr, nullptr, nullptr);

    cudaStreamWaitEvent(0, evF3, 0);
    // gather(l7, idx3) @ w6 -> relu -> fused atomic max-pool into out
    tgemm_kernel<<<dim3((M3 + 127) / 128, 4), 256, TG_SMEM>>>(
        (long long)HOFF_L7, 384, (long long)(HOFF_WC + WC_W6), b6, -1LL,
        0LL, 512, M3, 512, 384, 1, IDX3, S3, S2,
        -1LL, nullptr, out, nullptr, nullptr, nullptr, nullptr);
}